// round 8
// baseline (speedup 1.0000x reference)
#include <cuda_runtime.h>

// Fixed problem shape
constexpr int B_  = 32;
constexpr int C_  = 256;
constexpr int N_  = 4608;         // 96*48
constexpr int N4  = N_ / 4;       // 1152
constexpr int N2  = N_ / 2;       // 2304 float2 per row

// Batch split: x chunk per split = 8 * 4.7 MB = 37.7 MB << L2 (~120 MB)
constexpr int SPLITS = 4;
constexpr int BH     = B_ / SPLITS;   // 8

// k1: float2 per thread (2 n), C split into 8 groups of 32 channels
constexpr int K1T       = 128;
constexpr int CH        = 8;
constexpr int CHC       = C_ / CH;    // 32 channels per block
constexpr int NTM       = N2 / K1T;   // 18 tiles (256 n each)
constexpr int K1_UNROLL = 16;

// k3: one (b,c) row per block
constexpr int K3T = 384;

// Scratch (__device__ globals: allocation-free rule)
__device__ float2   g_G[CH][B_ * N2];
__device__ float2   g_P[CH][B_ * N2];
__device__ float2   g_T[CH][B_ * N2];
__device__ float    g_theta[B_ * N_];
__device__ float    g_sp[B_ * NTM];
__device__ unsigned g_cnt[B_ * NTM];   // zero-init; self-resetting

// ---------------------------------------------------------------------------
// Kernel 1: partial dots over a 32-channel group (float2 per thread).
// Last-arriving block of each (b,tile) merges the CH partials: writes theta
// (+bias) and the tile's sum(phi*g) partial. Deterministic (fixed-order math
// on identical data regardless of which block merges).
// ---------------------------------------------------------------------------
__global__ __launch_bounds__(K1T)
void k1_dots(const float* __restrict__ x,
             const float* __restrict__ gw, const float* __restrict__ gb,
             const float* __restrict__ tw, const float* __restrict__ tb,
             const float* __restrict__ pw, const float* __restrict__ pb,
             int bbase)
{
    __shared__ float swt[3 * CHC];
    const int tid  = threadIdx.x;
    const int tile = blockIdx.x;
    const int ch   = blockIdx.y;
    const int b    = bbase + blockIdx.z;

    if (tid < CHC) {
        swt[tid]           = gw[ch * CHC + tid];
        swt[CHC + tid]     = tw[ch * CHC + tid];
        swt[2 * CHC + tid] = pw[ch * CHC + tid];
    }
    __syncthreads();

    const int n2 = tile * K1T + tid;
    const float2* xr = reinterpret_cast<const float2*>(x)
                       + ((size_t)b * C_ + (size_t)ch * CHC) * N2 + n2;

    float2 ga = make_float2(0.f, 0.f);
    float2 ta = make_float2(0.f, 0.f);
    float2 pa = make_float2(0.f, 0.f);

    #pragma unroll
    for (int c0 = 0; c0 < CHC; c0 += K1_UNROLL) {
        float2 xv[K1_UNROLL];
        #pragma unroll
        for (int j = 0; j < K1_UNROLL; j++)
            xv[j] = __ldg(xr + (size_t)(c0 + j) * N2);
        #pragma unroll
        for (int j = 0; j < K1_UNROLL; j++) {
            const int c = c0 + j;
            const float w0 = swt[c];
            const float w1 = swt[CHC + c];
            const float w2 = swt[2 * CHC + c];
            ga.x = fmaf(w0, xv[j].x, ga.x); ga.y = fmaf(w0, xv[j].y, ga.y);
            ta.x = fmaf(w1, xv[j].x, ta.x); ta.y = fmaf(w1, xv[j].y, ta.y);
            pa.x = fmaf(w2, xv[j].x, pa.x); pa.y = fmaf(w2, xv[j].y, pa.y);
        }
    }

    const size_t o = (size_t)b * N2 + n2;
    g_G[ch][o] = ga;
    g_T[ch][o] = ta;
    g_P[ch][o] = pa;

    // -------- last-arriver merge (threadFenceReduction pattern) --------
    __threadfence();
    __syncthreads();
    __shared__ int sLast;
    if (tid == 0) {
        const int idx = b * NTM + tile;
        const unsigned old = atomicAdd(&g_cnt[idx], 1u);
        const int last = (old == CH - 1);
        if (last) g_cnt[idx] = 0;          // self-reset for next launch
        sLast = last;
    }
    __syncthreads();
    if (!sLast) return;

    const float gb0 = __ldg(gb), tb0 = __ldg(tb), pb0 = __ldg(pb);

    float2 G = make_float2(gb0, gb0);
    float2 P = make_float2(pb0, pb0);
    float2 T = make_float2(tb0, tb0);
    #pragma unroll
    for (int h = 0; h < CH; h++) {         // fixed order
        const float2 gv = g_G[h][o]; G.x += gv.x; G.y += gv.y;
        const float2 pv = g_P[h][o]; P.x += pv.x; P.y += pv.y;
        const float2 tv = g_T[h][o]; T.x += tv.x; T.y += tv.y;
    }
    reinterpret_cast<float2*>(g_theta)[o] = T;

    float pg = G.x * P.x + G.y * P.y;
    #pragma unroll
    for (int off = 16; off > 0; off >>= 1)
        pg += __shfl_xor_sync(0xffffffffu, pg, off);

    __shared__ float red[K1T / 32];
    if ((tid & 31) == 0) red[tid >> 5] = pg;
    __syncthreads();
    if (tid == 0) {
        float s = 0.f;
        #pragma unroll
        for (int w = 0; w < K1T / 32; w++) s += red[w];
        g_sp[b * NTM + tile] = s;
    }
}

// ---------------------------------------------------------------------------
// Kernel 3: z = theta[b,n]*ca + cd + x[b,c,n], one (b,c) row per block.
// x of this split is L2-resident from k1 (37.7 MB chunk); __ldcs drops the
// line after the read so the next split's x can take over L2.
// ---------------------------------------------------------------------------
__global__ __launch_bounds__(K3T)
void k3_epilogue(const float* __restrict__ x, float* __restrict__ z,
                 const float* __restrict__ Ww, const float* __restrict__ Wb,
                 const float* __restrict__ gamma, const float* __restrict__ beta,
                 const float* __restrict__ mean,  const float* __restrict__ var,
                 int bbase)
{
    const int c = blockIdx.x;
    const int b = bbase + blockIdx.y;

    float s = 0.f;
    #pragma unroll
    for (int t = 0; t < NTM; t++) s += g_sp[b * NTM + t];   // fixed order
    s *= (1.f / (float)N_);

    const float inv = __ldg(gamma + c) * rsqrtf(__ldg(var + c) + 1e-5f);
    const float ca  = s * __ldg(Ww + c) * inv;
    const float cd  = (__ldg(Wb + c) - __ldg(mean + c)) * inv + __ldg(beta + c);

    const size_t row = ((size_t)b * C_ + c) * N4;
    const float4* xr = reinterpret_cast<const float4*>(x) + row;
    float4*       zr = reinterpret_cast<float4*>(z) + row;
    const float4* th = reinterpret_cast<const float4*>(g_theta) + (size_t)b * N4;

    #pragma unroll
    for (int k = 0; k < N4 / K3T; k++) {
        const int i = k * K3T + threadIdx.x;
        const float4 tv = __ldg(th + i);
        const float4 xv = __ldcs(xr + i);      // L2 hit; evict-first after use
        float4 o;
        o.x = fmaf(tv.x, ca, cd) + xv.x;
        o.y = fmaf(tv.y, ca, cd) + xv.y;
        o.z = fmaf(tv.z, ca, cd) + xv.z;
        o.w = fmaf(tv.w, ca, cd) + xv.w;
        __stcs(zr + i, o);                     // streaming store
    }
}

// ---------------------------------------------------------------------------
extern "C" void kernel_launch(void* const* d_in, const int* in_sizes, int n_in,
                              void* d_out, int out_size)
{
    const float* x     = (const float*)d_in[0];
    const float* g_w   = (const float*)d_in[1];
    const float* g_b   = (const float*)d_in[2];
    const float* th_w  = (const float*)d_in[3];
    const float* th_b  = (const float*)d_in[4];
    const float* ph_w  = (const float*)d_in[5];
    const float* ph_b  = (const float*)d_in[6];
    const float* W_w   = (const float*)d_in[7];
    const float* W_b   = (const float*)d_in[8];
    const float* gamma = (const float*)d_in[9];
    const float* beta  = (const float*)d_in[10];
    const float* mean  = (const float*)d_in[11];
    const float* var   = (const float*)d_in[12];
    float* z = (float*)d_out;

    for (int h = 0; h < SPLITS; h++) {
        const int bbase = h * BH;
        dim3 g1(NTM, CH, BH);
        k1_dots<<<g1, K1T>>>(x, g_w, g_b, th_w, th_b, ph_w, ph_b, bbase);
        dim3 g3(C_, BH);
        k3_epilogue<<<g3, K3T>>>(x, z, W_w, W_b, gamma, beta, mean, var, bbase);
    }
}

// round 9
// speedup vs baseline: 1.1187x; 1.1187x over previous
#include <cuda_runtime.h>

// Fixed problem shape
constexpr int B_  = 32;
constexpr int C_  = 256;
constexpr int N_  = 4608;         // 96*48
constexpr int N4  = N_ / 4;       // 1152
constexpr int N2  = N_ / 2;       // 2304 float2 per row

// Batch split: x chunk per split = 8 * 4.7 MB = 37.7 MB << L2
constexpr int SPLITS = 4;
constexpr int BH     = B_ / SPLITS;   // 8

// k1: float2 per thread (2 n), C split into 8 groups of 32 channels
constexpr int K1T       = 128;
constexpr int CH        = 8;
constexpr int CHC       = C_ / CH;    // 32 channels per block
constexpr int NTM       = N2 / K1T;   // 18 tiles
constexpr int K1_UNROLL = 16;

// k3: 288 threads, 2 channel-rows per block (one-wave grid: 1024 blocks)
constexpr int K3T  = 288;
constexpr int K3R  = 2;               // rows (channels) per block
constexpr int K3IT = N4 / K3T;        // 4

// Scratch (__device__ globals: allocation-free rule)
__device__ float2   g_G[CH][B_ * N2];
__device__ float2   g_P[CH][B_ * N2];
__device__ float2   g_T[CH][B_ * N2];
__device__ float    g_theta[B_ * N_];
__device__ float    g_sp[B_ * NTM];
__device__ unsigned g_cnt[B_ * NTM];   // zero-init; self-resetting

// ---------------------------------------------------------------------------
// Kernel 1: partial dots over a 32-channel group (float2 per thread).
// Last-arriving block of each (b,tile) merges the CH partials (fixed-order
// math on identical data => deterministic).
// ---------------------------------------------------------------------------
__global__ __launch_bounds__(K1T)
void k1_dots(const float* __restrict__ x,
             const float* __restrict__ gw, const float* __restrict__ gb,
             const float* __restrict__ tw, const float* __restrict__ tb,
             const float* __restrict__ pw, const float* __restrict__ pb,
             int bbase)
{
    __shared__ float swt[3 * CHC];
    const int tid  = threadIdx.x;
    const int tile = blockIdx.x;
    const int ch   = blockIdx.y;
    const int b    = bbase + blockIdx.z;

    if (tid < CHC) {
        swt[tid]           = gw[ch * CHC + tid];
        swt[CHC + tid]     = tw[ch * CHC + tid];
        swt[2 * CHC + tid] = pw[ch * CHC + tid];
    }
    __syncthreads();

    const int n2 = tile * K1T + tid;
    const float2* xr = reinterpret_cast<const float2*>(x)
                       + ((size_t)b * C_ + (size_t)ch * CHC) * N2 + n2;

    float2 ga = make_float2(0.f, 0.f);
    float2 ta = make_float2(0.f, 0.f);
    float2 pa = make_float2(0.f, 0.f);

    #pragma unroll
    for (int c0 = 0; c0 < CHC; c0 += K1_UNROLL) {
        float2 xv[K1_UNROLL];
        #pragma unroll
        for (int j = 0; j < K1_UNROLL; j++)
            xv[j] = __ldg(xr + (size_t)(c0 + j) * N2);
        #pragma unroll
        for (int j = 0; j < K1_UNROLL; j++) {
            const int c = c0 + j;
            const float w0 = swt[c];
            const float w1 = swt[CHC + c];
            const float w2 = swt[2 * CHC + c];
            ga.x = fmaf(w0, xv[j].x, ga.x); ga.y = fmaf(w0, xv[j].y, ga.y);
            ta.x = fmaf(w1, xv[j].x, ta.x); ta.y = fmaf(w1, xv[j].y, ta.y);
            pa.x = fmaf(w2, xv[j].x, pa.x); pa.y = fmaf(w2, xv[j].y, pa.y);
        }
    }

    const size_t o = (size_t)b * N2 + n2;
    g_G[ch][o] = ga;
    g_T[ch][o] = ta;
    g_P[ch][o] = pa;

    // -------- last-arriver merge --------
    __threadfence();
    __syncthreads();
    __shared__ int sLast;
    if (tid == 0) {
        const int idx = b * NTM + tile;
        const unsigned old = atomicAdd(&g_cnt[idx], 1u);
        const int last = (old == CH - 1);
        if (last) g_cnt[idx] = 0;          // self-reset for next launch
        sLast = last;
    }
    __syncthreads();
    if (!sLast) return;

    const float gb0 = __ldg(gb), tb0 = __ldg(tb), pb0 = __ldg(pb);

    float2 G = make_float2(gb0, gb0);
    float2 P = make_float2(pb0, pb0);
    float2 T = make_float2(tb0, tb0);
    #pragma unroll
    for (int h = 0; h < CH; h++) {         // fixed order
        const float2 gv = g_G[h][o]; G.x += gv.x; G.y += gv.y;
        const float2 pv = g_P[h][o]; P.x += pv.x; P.y += pv.y;
        const float2 tv = g_T[h][o]; T.x += tv.x; T.y += tv.y;
    }
    reinterpret_cast<float2*>(g_theta)[o] = T;

    float pg = G.x * P.x + G.y * P.y;
    #pragma unroll
    for (int off = 16; off > 0; off >>= 1)
        pg += __shfl_xor_sync(0xffffffffu, pg, off);

    __shared__ float red[K1T / 32];
    if ((tid & 31) == 0) red[tid >> 5] = pg;
    __syncthreads();
    if (tid == 0) {
        float s = 0.f;
        #pragma unroll
        for (int w = 0; w < K1T / 32; w++) s += red[w];
        g_sp[b * NTM + tile] = s;
    }
}

// ---------------------------------------------------------------------------
// Kernel 3: z = theta[b,n]*ca[c] + cd[c] + x[b,c,n], 2 channels per block.
// One-wave grid + immediate PDL trigger so the next split's k1 overlaps.
// theta loaded once per i, reused for both channel rows.
// ---------------------------------------------------------------------------
__global__ __launch_bounds__(K3T)
void k3_epilogue(const float* __restrict__ x, float* __restrict__ z,
                 const float* __restrict__ Ww, const float* __restrict__ Wb,
                 const float* __restrict__ gamma, const float* __restrict__ beta,
                 const float* __restrict__ mean,  const float* __restrict__ var,
                 int bbase)
{
#if __CUDA_ARCH__ >= 900
    cudaTriggerProgrammaticLaunchCompletion();   // release next split's k1
#endif
    const int b   = bbase + blockIdx.y;
    const int tid = threadIdx.x;

    float s = 0.f;
    #pragma unroll
    for (int t = 0; t < NTM; t++) s += g_sp[b * NTM + t];   // fixed order
    s *= (1.f / (float)N_);

    float ca[K3R], cd[K3R];
    const float4* xr[K3R];
    float4*       zr[K3R];
    #pragma unroll
    for (int r = 0; r < K3R; r++) {
        const int c = blockIdx.x * K3R + r;
        const float inv = __ldg(gamma + c) * rsqrtf(__ldg(var + c) + 1e-5f);
        ca[r] = s * __ldg(Ww + c) * inv;
        cd[r] = (__ldg(Wb + c) - __ldg(mean + c)) * inv + __ldg(beta + c);
        const size_t row = ((size_t)b * C_ + c) * N4;
        xr[r] = reinterpret_cast<const float4*>(x) + row;
        zr[r] = reinterpret_cast<float4*>(z) + row;
    }

    const float4* th = reinterpret_cast<const float4*>(g_theta) + (size_t)b * N4;

    #pragma unroll
    for (int k = 0; k < K3IT; k++) {
        const int i = k * K3T + tid;
        const float4 tv = __ldg(th + i);      // shared across both rows
        #pragma unroll
        for (int r = 0; r < K3R; r++) {
            const float4 xv = __ldcs(xr[r] + i);   // L2 hit; evict after use
            float4 o;
            o.x = fmaf(tv.x, ca[r], cd[r]) + xv.x;
            o.y = fmaf(tv.y, ca[r], cd[r]) + xv.y;
            o.z = fmaf(tv.z, ca[r], cd[r]) + xv.z;
            o.w = fmaf(tv.w, ca[r], cd[r]) + xv.w;
            __stcs(zr[r] + i, o);                  // streaming store
        }
    }
}

// ---------------------------------------------------------------------------
extern "C" void kernel_launch(void* const* d_in, const int* in_sizes, int n_in,
                              void* d_out, int out_size)
{
    const float* x     = (const float*)d_in[0];
    const float* g_w   = (const float*)d_in[1];
    const float* g_b   = (const float*)d_in[2];
    const float* th_w  = (const float*)d_in[3];
    const float* th_b  = (const float*)d_in[4];
    const float* ph_w  = (const float*)d_in[5];
    const float* ph_b  = (const float*)d_in[6];
    const float* W_w   = (const float*)d_in[7];
    const float* W_b   = (const float*)d_in[8];
    const float* gamma = (const float*)d_in[9];
    const float* beta  = (const float*)d_in[10];
    const float* mean  = (const float*)d_in[11];
    const float* var   = (const float*)d_in[12];
    float* z = (float*)d_out;

    for (int h = 0; h < SPLITS; h++) {
        const int bbase = h * BH;
        dim3 g1(NTM, CH, BH);

        if (h == 0) {
            k1_dots<<<g1, K1T>>>(x, g_w, g_b, th_w, th_b, ph_w, ph_b, bbase);
        } else {
            // PDL: overlap this k1 with the preceding split's k3.
            cudaLaunchConfig_t cfg = {};
            cfg.gridDim  = g1;
            cfg.blockDim = dim3(K1T, 1, 1);
            cfg.dynamicSmemBytes = 0;
            cfg.stream = 0;
            cudaLaunchAttribute at[1];
            at[0].id = cudaLaunchAttributeProgrammaticStreamSerialization;
            at[0].val.programmaticStreamSerializationAllowed = 1;
            cfg.attrs = at;
            cfg.numAttrs = 1;
            cudaLaunchKernelEx(&cfg, k1_dots,
                               x, g_w, g_b, th_w, th_b, ph_w, ph_b, bbase);
        }

        dim3 g3(C_ / K3R, BH);   // 128 x 8 = 1024 blocks (one wave)
        k3_epilogue<<<g3, K3T>>>(x, z, W_w, W_b, gamma, beta, mean, var, bbase);
    }
}